// round 14
// baseline (speedup 1.0000x reference)
#include <cuda_runtime.h>
#include <cuda_fp16.h>
#include <math.h>
#include <stdint.h>

#define B_ 16
#define L_ 2048
#define D_ 256

// Scratch (static device arrays — no allocation allowed)
__device__ __align__(16) __half g_scoreH[(size_t)B_ * L_ * L_];   // [b][i][j-perm], tril(+zero superdiag)
__device__ __align__(16) __half g_embTH[(size_t)B_ * D_ * L_];    // [b][d][j-perm]
__device__ __align__(16) __half g_hiddenH[(size_t)B_ * L_ * D_];  // [b][i][k-perm]
__device__ __align__(16) __half g_noiseH[(size_t)B_ * L_ * D_];   // [b][i][k-perm]
__device__ __align__(16) __half g_WpH[512 * 256];                 // [n][k=512 perm]

// ---------------------------------------------------------------------------
// helpers
// ---------------------------------------------------------------------------
__device__ __forceinline__ float softplusf_(float x) {
    return fmaxf(x, 0.f) + log1pf(__expf(-fabsf(x)));
}
__device__ __forceinline__ float sigmoidf_(float x) {
    return 1.f / (1.f + __expf(-x));
}
__device__ __forceinline__ uint32_t h2_(float lo, float hi) {
    __half2 h = __floats2half2_rn(lo, hi);
    return *(uint32_t*)&h;
}
__device__ __forceinline__ uint32_t s2u_(const void* p) {
    uint32_t a;
    asm("{ .reg .u64 t; cvta.to.shared.u64 t, %1; cvt.u32.u64 %0, t; }" : "=r"(a) : "l"(p));
    return a;
}
__device__ __forceinline__ void cpa16_(uint32_t dst, const void* src) {
    asm volatile("cp.async.cg.shared.global [%0], [%1], 16;" :: "r"(dst), "l"(src) : "memory");
}
#define CPA_COMMIT_ asm volatile("cp.async.commit_group;" ::: "memory")
#define CPA_WAIT0_  asm volatile("cp.async.wait_group 0;" ::: "memory")

__device__ __forceinline__ void mma16_(float* c, uint32_t a0, uint32_t a1, uint32_t a2,
                                       uint32_t a3, uint32_t b0, uint32_t b1) {
    asm volatile(
        "mma.sync.aligned.m16n8k16.row.col.f32.f16.f16.f32 "
        "{%0,%1,%2,%3}, {%4,%5,%6,%7}, {%8,%9}, {%0,%1,%2,%3};"
        : "+f"(c[0]), "+f"(c[1]), "+f"(c[2]), "+f"(c[3])
        : "r"(a0), "r"(a1), "r"(a2), "r"(a3), "r"(b0), "r"(b1));
}

// K=128 chunks, each = two 64-k sub-tiles with the proven XOR-16 swizzle layout.
// smem: A 2x32KB | B 2x64KB | params 2KB  (192KB stages + 2KB)
#define KOFF_A0  0
#define KOFF_A1  32768
#define KOFF_B0  65536
#define KOFF_B1  131072
#define KOFF_PRM 196608
#define KSM_TOT  198656

// ---------------------------------------------------------------------------
// fused prep kernel: sections (blockIdx ranges): scores | embTH | noiseH | wpH
// (R12 layout: 1 uint32 per thread, warp-local 256B windows — L1-friendly;
//  __sinf/__cosf intrinsics in the emb section.)
// ---------------------------------------------------------------------------
#define NB_SCORE (528 * B_)                       // 8448
#define NB_EMB   ((B_ * D_ * L_ / 2) / 256)       // 16384
#define NB_NOISE ((B_ * L_ * D_ / 2) / 256)       // 16384
#define NB_WP    ((256 * 512 / 2) / 256)          // 256
#define NB_TOT   (NB_SCORE + NB_EMB + NB_NOISE + NB_WP)

__global__ __launch_bounds__(256) void prep_kernel(
    const float* __restrict__ et, const float* __restrict__ gp,
    const float* __restrict__ lsc, const float* __restrict__ noise,
    const float* __restrict__ Wn, const float* __restrict__ Wi)
{
    const int bid = blockIdx.x;
    const int tid = threadIdx.x;

    if (bid < NB_SCORE) {
        // ---- scores: lower-triangle 64x64 tiles (+zero superdiag tiles) ----
        __shared__ float ei[64], ej[64];
        __shared__ uint32_t sct[64 * 33];

        const int b = bid / 528, tt = bid % 528;
        int it = (int)((sqrtf(8.f * (float)tt + 1.f) - 1.f) * 0.5f);
        while ((it + 1) * (it + 2) / 2 <= tt) ++it;
        while (it * (it + 1) / 2 > tt) --it;
        const int jt = tt - it * (it + 1) / 2;

        if (tid < 64) ei[tid] = __ldg(&et[b * L_ + it * 64 + tid]);
        else if (tid < 128) ej[tid - 64] = __ldg(&et[b * L_ + jt * 64 + (tid - 64)]);

        const float ls      = softplusf_(lsc[0]);
        const float inv_ls2 = 1.f / (ls * ls);
        const float inv_s   = 1.f / sigmoidf_(gp[1]);
        const float c1      = inv_s * 0.005f;
        const float c0      = -sigmoidf_(gp[0]) * inv_s;
        __syncthreads();

        const int il = tid >> 2, jseg = (tid & 3) * 16;
        const float ti = ei[il];
        const int ig = it * 64 + il;
#pragma unroll
        for (int q = 0; q < 16; q += 2) {
            float sv[2];
#pragma unroll
            for (int e = 0; e < 2; ++e) {
                const int jl = jseg + q + e;
                const float dd = fabsf(ti - ej[jl]);
                const float kv = __expf(-dd * dd * inv_ls2);
                float th;
                asm("tanh.approx.f32 %0, %1;" : "=f"(th) : "f"(fmaf(dd, c1, c0)));
                float s = fmaf(kv, th, kv);
                if (jt * 64 + jl > ig) s = 0.f;   // causal (keep diagonal)
                sv[e] = s;
            }
            sct[il * 33 + (jseg + q) / 2] = h2_(sv[0], sv[1]);
        }
        __syncthreads();

        const int w = tid >> 5, l = tid & 31;
        const int p = (l & 7) * 4 + (l >> 3);   // inverse pair-perm
        char* base = (char*)g_scoreH + ((size_t)(b * L_ + it * 64) * L_ + jt * 64) * 2;
#pragma unroll
        for (int rr = 0; rr < 8; ++rr) {
            const int r = w * 8 + rr;
            *(uint32_t*)(base + (size_t)r * (L_ * 2) + l * 4) = sct[r * 33 + p];
        }
        if (it == jt && it < 31) {   // zero the tile right of the diagonal
            char* zb = (char*)g_scoreH + ((size_t)(b * L_ + it * 64) * L_ + (jt + 1) * 64) * 2;
#pragma unroll
            for (int rr = 0; rr < 8; ++rr) {
                const int r = w * 8 + rr;
                *(uint32_t*)(zb + (size_t)r * (L_ * 2) + l * 4) = 0u;
            }
        }
    } else if (bid < NB_SCORE + NB_EMB) {
        // ---- emb^T (half, pair-permuted along j) — fast sin/cos ----
        const int idx = (bid - NB_SCORE) * 256 + tid;
        const int l = idx & 31, blk = (idx >> 5) & 31, d = (idx >> 10) & 255, b = idx >> 18;
        const int p = (l & 7) * 4 + (l >> 3);
        const int j = blk * 64 + 2 * p;
        const float f = exp2f(-0.10381025296522991f * (float)d);
        const float a0 = __ldg(&et[b * L_ + j]) * f;
        const float a1 = __ldg(&et[b * L_ + j + 1]) * f;
        const float v0 = (d & 1) ? __cosf(a0) : __sinf(a0);
        const float v1 = (d & 1) ? __cosf(a1) : __sinf(a1);
        *(uint32_t*)((char*)g_embTH + ((size_t)(b * 256 + d) * L_ + blk * 64) * 2 + l * 4) =
            h2_(v0, v1);
    } else if (bid < NB_SCORE + NB_EMB + NB_NOISE) {
        // ---- noise (half, pair-permuted along k) ----
        const int idx = (bid - NB_SCORE - NB_EMB) * 256 + tid;
        const int l = idx & 31, blk = (idx >> 5) & 3, row = idx >> 7;
        const int p = (l & 7) * 4 + (l >> 3);
        const int k = blk * 64 + 2 * p;
        const float v0 = __ldg(&noise[(size_t)row * 256 + k]);
        const float v1 = __ldg(&noise[(size_t)row * 256 + k + 1]);
        *(uint32_t*)((char*)g_noiseH + (size_t)row * 512 + blk * 128 + l * 4) = h2_(v0, v1);
    } else {
        // ---- W = [Wn | Wi] rows (half, pair-permuted along k) ----
        const int idx = (bid - NB_SCORE - NB_EMB - NB_NOISE) * 256 + tid;
        const int l = idx & 31, blk = (idx >> 5) & 7, n = idx >> 8;
        const int p = (l & 7) * 4 + (l >> 3);
        const int k = blk * 64 + 2 * p;
        const float v0 = (k < 256) ? __ldg(&Wn[n * 256 + k]) : __ldg(&Wi[n * 256 + k - 256]);
        const float v1 = (k + 1 < 256) ? __ldg(&Wn[n * 256 + k + 1])
                                       : __ldg(&Wi[n * 256 + k + 1 - 256]);
        *(uint32_t*)((char*)g_WpH + (size_t)n * 1024 + blk * 128 + l * 4) = h2_(v0, v1);
    }
}

// ---------------------------------------------------------------------------
// k2: hidden = LN( tril(S) @ E ) — fp16 mma, K=128 chunks, balanced tile-pairs
// ---------------------------------------------------------------------------
__global__ __launch_bounds__(512) void k2_mma(
    const float* __restrict__ gamma, const float* __restrict__ beta)
{
    extern __shared__ char sm[];
    const uint32_t sb = s2u_(sm);
    float* gsm = (float*)(sm + KOFF_PRM);
    float* bsm = gsm + 256;
    float* ps  = (float*)sm;      // alias A0 (only at epilogue)
    float* pq  = ps + 512;

    const int tid = threadIdx.x, lane = tid & 31, warp = tid >> 5;
    const int g = lane >> 2, t = lane & 3, wm = warp >> 2, wn = warp & 3;
    if (tid < 256) { gsm[tid] = gamma[tid]; bsm[tid] = beta[tid]; }

    const int b = blockIdx.y;
    const char* Bbase = (const char*)g_embTH + (size_t)b * D_ * L_ * 2;

    for (int ph = 0; ph < 2; ++ph) {
        const int ib = ph == 0 ? 15 - (int)blockIdx.x : (int)blockIdx.x;
        const int i0 = ib * 128;
        const int nk = ib + 1;                                  // K=128 chunks
        const char* Abase = (const char*)g_scoreH + (size_t)(b * L_ + i0) * L_ * 2;

        auto pref = [&](int kt, uint32_t ao, uint32_t bo) {
            const int j0b = kt * 256;   // byte offset of chunk within row
#pragma unroll
            for (int sub = 0; sub < 2; ++sub) {
                const uint32_t asub = ao + sub * 16384;
                const uint32_t bsub = bo + sub * 32768;
                const int jb = j0b + sub * 128;
#pragma unroll
                for (int q = 0; q < 2; ++q) {
                    const int c = tid + 512 * q;
                    const int r = c >> 3, u = (c & 7) * 16;
                    cpa16_(sb + asub + r * 128 + (u ^ ((r & 7) << 4)),
                           Abase + (size_t)r * (L_ * 2) + jb + u);
                }
#pragma unroll
                for (int q = 0; q < 4; ++q) {
                    const int c = tid + 512 * q;
                    const int n = c >> 3, u = (c & 7) * 16;
                    cpa16_(sb + bsub + n * 128 + (u ^ ((n & 7) << 4)),
                           Bbase + (size_t)n * (L_ * 2) + jb + u);
                }
            }
            CPA_COMMIT_;
        };

        float acc[2][8][4];
#pragma unroll
        for (int mf = 0; mf < 2; ++mf)
#pragma unroll
            for (int nf = 0; nf < 8; ++nf)
#pragma unroll
                for (int e = 0; e < 4; ++e) acc[mf][nf][e] = 0.f;

        __syncthreads();               // params ready / ps-pq alias released
        pref(0, KOFF_A0, KOFF_B0);
        CPA_WAIT0_;
        __syncthreads();

        for (int kt = 0; kt < nk; ++kt) {
            const int s = kt & 1;
            const uint32_t ao = s ? KOFF_A1 : KOFF_A0;
            const uint32_t bo = s ? KOFF_B1 : KOFF_B0;
            if (kt + 1 < nk) pref(kt + 1, s ? KOFF_A0 : KOFF_A1, s ? KOFF_B0 : KOFF_B1);
#pragma unroll
            for (int sub = 0; sub < 2; ++sub) {
                const char* Ab = sm + ao + sub * 16384;
                const char* Bb = sm + bo + sub * 32768;
#pragma unroll
                for (int s2 = 0; s2 < 2; ++s2) {
                    const int toff = t * 32 + s2 * 16;
                    uint4 ar[2][2];
#pragma unroll
                    for (int mf = 0; mf < 2; ++mf) {
                        const int r0 = wm * 32 + mf * 16 + g;
                        ar[mf][0] = *(const uint4*)(Ab + r0 * 128 + (toff ^ ((r0 & 7) << 4)));
                        const int r1 = r0 + 8;
                        ar[mf][1] = *(const uint4*)(Ab + r1 * 128 + (toff ^ ((r1 & 7) << 4)));
                    }
#pragma unroll
                    for (int nf = 0; nf < 8; ++nf) {
                        const int n = wn * 64 + nf * 8 + g;
                        const uint4 br = *(const uint4*)(Bb + n * 128 + (toff ^ ((n & 7) << 4)));
                        mma16_(acc[0][nf], ar[0][0].x, ar[0][1].x, ar[0][0].y, ar[0][1].y, br.x, br.y);
                        mma16_(acc[1][nf], ar[1][0].x, ar[1][1].x, ar[1][0].y, ar[1][1].y, br.x, br.y);
                        mma16_(acc[0][nf], ar[0][0].z, ar[0][1].z, ar[0][0].w, ar[0][1].w, br.z, br.w);
                        mma16_(acc[1][nf], ar[1][0].z, ar[1][1].z, ar[1][0].w, ar[1][1].w, br.z, br.w);
                    }
                }
            }
            CPA_WAIT0_;
            __syncthreads();
        }

        // LN epilogue
#pragma unroll
        for (int mf = 0; mf < 2; ++mf)
#pragma unroll
            for (int h = 0; h < 2; ++h) {
                float s = 0.f, q2 = 0.f;
#pragma unroll
                for (int nf = 0; nf < 8; ++nf) {
                    const float v0 = acc[mf][nf][2 * h], v1 = acc[mf][nf][2 * h + 1];
                    s += v0 + v1;
                    q2 = fmaf(v0, v0, fmaf(v1, v1, q2));
                }
                s  += __shfl_xor_sync(0xffffffffu, s, 1);
                s  += __shfl_xor_sync(0xffffffffu, s, 2);
                q2 += __shfl_xor_sync(0xffffffffu, q2, 1);
                q2 += __shfl_xor_sync(0xffffffffu, q2, 2);
                if (t == 0) {
                    const int r = wm * 32 + mf * 16 + h * 8 + g;
                    ps[r * 4 + wn] = s; pq[r * 4 + wn] = q2;
                }
            }
        __syncthreads();

#pragma unroll
        for (int mf = 0; mf < 2; ++mf)
#pragma unroll
            for (int h = 0; h < 2; ++h) {
                const int r = wm * 32 + mf * 16 + h * 8 + g;
                const float su = ps[r * 4] + ps[r * 4 + 1] + ps[r * 4 + 2] + ps[r * 4 + 3];
                const float sq = pq[r * 4] + pq[r * 4 + 1] + pq[r * 4 + 2] + pq[r * 4 + 3];
                const float mu  = su * (1.f / 256.f);
                const float var = fmaxf(sq * (1.f / 256.f) - mu * mu, 0.f);
                const float rs  = rsqrtf(var + 1e-6f);
                char* dst = (char*)g_hiddenH + (size_t)(b * L_ + i0 + r) * 512;
#pragma unroll
                for (int nf = 0; nf < 8; ++nf) {
                    const int c = wn * 64 + nf * 8 + 2 * t;
                    const float o0 = (acc[mf][nf][2 * h + 0] - mu) * rs * gsm[c] + bsm[c];
                    const float o1 = (acc[mf][nf][2 * h + 1] - mu) * rs * gsm[c + 1] + bsm[c + 1];
                    const int p = (c & 63) >> 1;
                    const int pp = (p & 3) * 8 + (p >> 2);
                    *(uint32_t*)(dst + (c >> 6) * 128 + pp * 4) = h2_(o0, o1);
                }
            }
    }
}

// ---------------------------------------------------------------------------
// k3: out = softplus( w_time . relu([noise|hidden] @ [Wn;Wi]^T) + b )
// K=512 -> 4 chunks of 128.
// ---------------------------------------------------------------------------
__global__ __launch_bounds__(512) void k3_mma(
    const float* __restrict__ wt, const float* __restrict__ btime,
    float* __restrict__ out)
{
    extern __shared__ char sm[];
    const uint32_t sb = s2u_(sm);
    float* wsm = (float*)(sm + KOFF_PRM);
    float* pp  = (float*)sm;   // alias A0 after mainloop

    const int tid = threadIdx.x, lane = tid & 31, warp = tid >> 5;
    const int g = lane >> 2, t = lane & 3, wm = warp >> 2, wn = warp & 3;
    if (tid < 256) wsm[tid] = wt[tid];

    const int b  = blockIdx.y;
    const int i0 = blockIdx.x * 128;

    auto pref = [&](int kt, uint32_t ao, uint32_t bo) {
#pragma unroll
        for (int sub = 0; sub < 2; ++sub) {
            const int ko = 2 * kt + sub;     // 64-wide sub-chunk index (0..7)
            const uint32_t asub = ao + sub * 16384;
            const uint32_t bsub = bo + sub * 32768;
            const char* Asrc = (ko < 4)
                ? (const char*)g_noiseH + (size_t)(b * L_ + i0) * 512 + ko * 128
                : (const char*)g_hiddenH + (size_t)(b * L_ + i0) * 512 + (ko - 4) * 128;
#pragma unroll
            for (int q = 0; q < 2; ++q) {
                const int c = tid + 512 * q;
                const int r = c >> 3, u = (c & 7) * 16;
                cpa16_(sb + asub + r * 128 + (u ^ ((r & 7) << 4)), Asrc + (size_t)r * 512 + u);
            }
#pragma unroll
            for (int q = 0; q < 4; ++q) {
                const int c = tid + 512 * q;
                const int n = c >> 3, u = (c & 7) * 16;
                cpa16_(sb + bsub + n * 128 + (u ^ ((n & 7) << 4)),
                       (const char*)g_WpH + (size_t)n * 1024 + ko * 128 + u);
            }
        }
        CPA_COMMIT_;
    };

    float acc[2][8][4];
#pragma unroll
    for (int mf = 0; mf < 2; ++mf)
#pragma unroll
        for (int nf = 0; nf < 8; ++nf)
#pragma unroll
            for (int e = 0; e < 4; ++e) acc[mf][nf][e] = 0.f;

    __syncthreads();
    pref(0, KOFF_A0, KOFF_B0);
    CPA_WAIT0_;
    __syncthreads();

    for (int kt = 0; kt < 4; ++kt) {
        const int s = kt & 1;
        const uint32_t ao = s ? KOFF_A1 : KOFF_A0;
        const uint32_t bo = s ? KOFF_B1 : KOFF_B0;
        if (kt < 3) pref(kt + 1, s ? KOFF_A0 : KOFF_A1, s ? KOFF_B0 : KOFF_B1);
#pragma unroll
        for (int sub = 0; sub < 2; ++sub) {
            const char* Ab = sm + ao + sub * 16384;
            const char* Bb = sm + bo + sub * 32768;
#pragma unroll
            for (int s2 = 0; s2 < 2; ++s2) {
                const int toff = t * 32 + s2 * 16;
                uint4 ar[2][2];
#pragma unroll
                for (int mf = 0; mf < 2; ++mf) {
                    const int r0 = wm * 32 + mf * 16 + g;
                    ar[mf][0] = *(const uint4*)(Ab + r0 * 128 + (toff ^ ((r0 & 7) << 4)));
                    const int r1 = r0 + 8;
                    ar[mf][1] = *(const uint4*)(Ab + r1 * 128 + (toff ^ ((r1 & 7) << 4)));
                }
#pragma unroll
                for (int nf = 0; nf < 8; ++nf) {
                    const int n = wn * 64 + nf * 8 + g;
                    const uint4 br = *(const uint4*)(Bb + n * 128 + (toff ^ ((n & 7) << 4)));
                    mma16_(acc[0][nf], ar[0][0].x, ar[0][1].x, ar[0][0].y, ar[0][1].y, br.x, br.y);
                    mma16_(acc[1][nf], ar[1][0].x, ar[1][1].x, ar[1][0].y, ar[1][1].y, br.x, br.y);
                    mma16_(acc[0][nf], ar[0][0].z, ar[0][1].z, ar[0][0].w, ar[0][1].w, br.z, br.w);
                    mma16_(acc[1][nf], ar[1][0].z, ar[1][1].z, ar[1][0].w, ar[1][1].w, br.z, br.w);
                }
            }
        }
        CPA_WAIT0_;
        __syncthreads();
    }

    // epilogue: relu + dot(w_time) partials -> quad reduce -> smem -> softplus
#pragma unroll
    for (int mf = 0; mf < 2; ++mf)
#pragma unroll
        for (int h = 0; h < 2; ++h) {
            float p = 0.f;
#pragma unroll
            for (int nf = 0; nf < 8; ++nf)
#pragma unroll
                for (int e = 0; e < 2; ++e) {
                    const int c = wn * 64 + nf * 8 + 2 * t + e;
                    p = fmaf(wsm[c], fmaxf(acc[mf][nf][2 * h + e], 0.f), p);
                }
            p += __shfl_xor_sync(0xffffffffu, p, 1);
            p += __shfl_xor_sync(0xffffffffu, p, 2);
            if (t == 0) pp[(wm * 32 + mf * 16 + h * 8 + g) * 4 + wn] = p;
        }
    __syncthreads();
    if (tid < 128) {
        const float s = pp[tid * 4] + pp[tid * 4 + 1] + pp[tid * 4 + 2] + pp[tid * 4 + 3];
        out[b * L_ + i0 + tid] = softplusf_(s + btime[0]);
    }
}

// ---------------------------------------------------------------------------
// Input order: 0 event_type (unused), 1 event_time, 2 noise, 3 gate_params,
// 4 length_scale, 5 Wn, 6 Wi, 7 w_time, 8 b_time, 9 ln_gamma, 10 ln_beta.
// ---------------------------------------------------------------------------
extern "C" void kernel_launch(void* const* d_in, const int* in_sizes, int n_in,
                              void* d_out, int out_size) {
    const float* et    = (const float*)d_in[1];
    const float* noise = (const float*)d_in[2];
    const float* gp    = (const float*)d_in[3];
    const float* lsc   = (const float*)d_in[4];
    const float* Wn    = (const float*)d_in[5];
    const float* Wi    = (const float*)d_in[6];
    const float* wt    = (const float*)d_in[7];
    const float* bt    = (const float*)d_in[8];
    const float* gam   = (const float*)d_in[9];
    const float* bet   = (const float*)d_in[10];
    float* out = (float*)d_out;

    cudaFuncSetAttribute(k2_mma, cudaFuncAttributeMaxDynamicSharedMemorySize, KSM_TOT);
    cudaFuncSetAttribute(k3_mma, cudaFuncAttributeMaxDynamicSharedMemorySize, KSM_TOT);

    prep_kernel<<<NB_TOT, 256>>>(et, gp, lsc, noise, Wn, Wi);
    k2_mma<<<dim3(8, B_), 512, KSM_TOT>>>(gam, bet);
    k3_mma<<<dim3(16, B_), 512, KSM_TOT>>>(wt, bt, out);
}

// round 15
// speedup vs baseline: 1.4777x; 1.4777x over previous
#include <cuda_runtime.h>
#include <cuda_fp16.h>
#include <math.h>
#include <stdint.h>

#define B_ 16
#define L_ 2048
#define D_ 256

// Scratch (static device arrays — no allocation allowed)
__device__ __align__(16) __half g_scoreH[(size_t)B_ * L_ * L_];   // [b][i][j-perm], tril(+zero superdiag)
__device__ __align__(16) __half g_embTH[(size_t)B_ * D_ * L_];    // [b][d][j-perm]
__device__ __align__(16) __half g_hiddenH[(size_t)B_ * L_ * D_];  // [b][i][k-perm]
__device__ __align__(16) __half g_noiseH[(size_t)B_ * L_ * D_];   // [b][i][k-perm]
__device__ __align__(16) __half g_WpH[512 * 256];                 // [n][k=512 perm]

// ---------------------------------------------------------------------------
// helpers
// ---------------------------------------------------------------------------
__device__ __forceinline__ float softplusf_(float x) {
    return fmaxf(x, 0.f) + log1pf(__expf(-fabsf(x)));
}
__device__ __forceinline__ float sigmoidf_(float x) {
    return 1.f / (1.f + __expf(-x));
}
__device__ __forceinline__ uint32_t h2_(float lo, float hi) {
    __half2 h = __floats2half2_rn(lo, hi);
    return *(uint32_t*)&h;
}
__device__ __forceinline__ uint32_t s2u_(const void* p) {
    uint32_t a;
    asm("{ .reg .u64 t; cvta.to.shared.u64 t, %1; cvt.u32.u64 %0, t; }" : "=r"(a) : "l"(p));
    return a;
}
__device__ __forceinline__ void cpa16_(uint32_t dst, const void* src) {
    asm volatile("cp.async.cg.shared.global [%0], [%1], 16;" :: "r"(dst), "l"(src) : "memory");
}
#define CPA_COMMIT_ asm volatile("cp.async.commit_group;" ::: "memory")
#define CPA_WAIT0_  asm volatile("cp.async.wait_group 0;" ::: "memory")

__device__ __forceinline__ void mma16_(float* c, uint32_t a0, uint32_t a1, uint32_t a2,
                                       uint32_t a3, uint32_t b0, uint32_t b1) {
    asm volatile(
        "mma.sync.aligned.m16n8k16.row.col.f32.f16.f16.f32 "
        "{%0,%1,%2,%3}, {%4,%5,%6,%7}, {%8,%9}, {%0,%1,%2,%3};"
        : "+f"(c[0]), "+f"(c[1]), "+f"(c[2]), "+f"(c[3])
        : "r"(a0), "r"(a1), "r"(a2), "r"(a3), "r"(b0), "r"(b1));
}

// K=128 chunks, each = two 64-k sub-tiles with the proven XOR-16 swizzle layout.
// smem: A 2x32KB | B 2x64KB | params 2KB  (192KB stages + 2KB)
#define KOFF_A0  0
#define KOFF_A1  32768
#define KOFF_B0  65536
#define KOFF_B1  131072
#define KOFF_PRM 196608
#define KSM_TOT  198656

// ---------------------------------------------------------------------------
// fused prep kernel: sections (blockIdx ranges): scores | embTH | noiseH | wpH
// (R12 layout: 1 uint32 per thread, warp-local 256B windows — L1-friendly)
// ---------------------------------------------------------------------------
#define NB_SCORE (528 * B_)                       // 8448
#define NB_EMB   ((B_ * D_ * L_ / 2) / 256)       // 16384
#define NB_NOISE ((B_ * L_ * D_ / 2) / 256)       // 16384
#define NB_WP    ((256 * 512 / 2) / 256)          // 256
#define NB_TOT   (NB_SCORE + NB_EMB + NB_NOISE + NB_WP)

__global__ __launch_bounds__(256) void prep_kernel(
    const float* __restrict__ et, const float* __restrict__ gp,
    const float* __restrict__ lsc, const float* __restrict__ noise,
    const float* __restrict__ Wn, const float* __restrict__ Wi)
{
    const int bid = blockIdx.x;
    const int tid = threadIdx.x;

    if (bid < NB_SCORE) {
        // ---- scores: lower-triangle 64x64 tiles (+zero superdiag tiles) ----
        __shared__ float ei[64], ej[64];
        __shared__ uint32_t sct[64 * 33];

        const int b = bid / 528, tt = bid % 528;
        int it = (int)((sqrtf(8.f * (float)tt + 1.f) - 1.f) * 0.5f);
        while ((it + 1) * (it + 2) / 2 <= tt) ++it;
        while (it * (it + 1) / 2 > tt) --it;
        const int jt = tt - it * (it + 1) / 2;

        if (tid < 64) ei[tid] = __ldg(&et[b * L_ + it * 64 + tid]);
        else if (tid < 128) ej[tid - 64] = __ldg(&et[b * L_ + jt * 64 + (tid - 64)]);

        const float ls      = softplusf_(lsc[0]);
        const float inv_ls2 = 1.f / (ls * ls);
        const float inv_s   = 1.f / sigmoidf_(gp[1]);
        const float c1      = inv_s * 0.005f;
        const float c0      = -sigmoidf_(gp[0]) * inv_s;
        __syncthreads();

        const int il = tid >> 2, jseg = (tid & 3) * 16;
        const float ti = ei[il];
        const int ig = it * 64 + il;
#pragma unroll
        for (int q = 0; q < 16; q += 2) {
            float sv[2];
#pragma unroll
            for (int e = 0; e < 2; ++e) {
                const int jl = jseg + q + e;
                const float dd = fabsf(ti - ej[jl]);
                const float kv = __expf(-dd * dd * inv_ls2);
                float th;
                asm("tanh.approx.f32 %0, %1;" : "=f"(th) : "f"(fmaf(dd, c1, c0)));
                float s = fmaf(kv, th, kv);
                if (jt * 64 + jl > ig) s = 0.f;   // causal (keep diagonal)
                sv[e] = s;
            }
            sct[il * 33 + (jseg + q) / 2] = h2_(sv[0], sv[1]);
        }
        __syncthreads();

        const int w = tid >> 5, l = tid & 31;
        const int p = (l & 7) * 4 + (l >> 3);   // inverse pair-perm
        char* base = (char*)g_scoreH + ((size_t)(b * L_ + it * 64) * L_ + jt * 64) * 2;
#pragma unroll
        for (int rr = 0; rr < 8; ++rr) {
            const int r = w * 8 + rr;
            *(uint32_t*)(base + (size_t)r * (L_ * 2) + l * 4) = sct[r * 33 + p];
        }
        if (it == jt && it < 31) {   // zero the tile right of the diagonal
            char* zb = (char*)g_scoreH + ((size_t)(b * L_ + it * 64) * L_ + (jt + 1) * 64) * 2;
#pragma unroll
            for (int rr = 0; rr < 8; ++rr) {
                const int r = w * 8 + rr;
                *(uint32_t*)(zb + (size_t)r * (L_ * 2) + l * 4) = 0u;
            }
        }
    } else if (bid < NB_SCORE + NB_EMB) {
        // ---- emb^T (half, pair-permuted along j) ----
        const int idx = (bid - NB_SCORE) * 256 + tid;
        const int l = idx & 31, blk = (idx >> 5) & 31, d = (idx >> 10) & 255, b = idx >> 18;
        const int p = (l & 7) * 4 + (l >> 3);
        const int j = blk * 64 + 2 * p;
        const float f = exp2f(-0.10381025296522991f * (float)d);
        const float a0 = __ldg(&et[b * L_ + j]) * f;
        const float a1 = __ldg(&et[b * L_ + j + 1]) * f;
        const float v0 = (d & 1) ? cosf(a0) : sinf(a0);
        const float v1 = (d & 1) ? cosf(a1) : sinf(a1);
        *(uint32_t*)((char*)g_embTH + ((size_t)(b * 256 + d) * L_ + blk * 64) * 2 + l * 4) =
            h2_(v0, v1);
    } else if (bid < NB_SCORE + NB_EMB + NB_NOISE) {
        // ---- noise (half, pair-permuted along k) ----
        const int idx = (bid - NB_SCORE - NB_EMB) * 256 + tid;
        const int l = idx & 31, blk = (idx >> 5) & 3, row = idx >> 7;
        const int p = (l & 7) * 4 + (l >> 3);
        const int k = blk * 64 + 2 * p;
        const float v0 = __ldg(&noise[(size_t)row * 256 + k]);
        const float v1 = __ldg(&noise[(size_t)row * 256 + k + 1]);
        *(uint32_t*)((char*)g_noiseH + (size_t)row * 512 + blk * 128 + l * 4) = h2_(v0, v1);
    } else {
        // ---- W = [Wn | Wi] rows (half, pair-permuted along k) ----
        const int idx = (bid - NB_SCORE - NB_EMB - NB_NOISE) * 256 + tid;
        const int l = idx & 31, blk = (idx >> 5) & 7, n = idx >> 8;
        const int p = (l & 7) * 4 + (l >> 3);
        const int k = blk * 64 + 2 * p;
        const float v0 = (k < 256) ? __ldg(&Wn[n * 256 + k]) : __ldg(&Wi[n * 256 + k - 256]);
        const float v1 = (k + 1 < 256) ? __ldg(&Wn[n * 256 + k + 1])
                                       : __ldg(&Wi[n * 256 + k + 1 - 256]);
        *(uint32_t*)((char*)g_WpH + (size_t)n * 1024 + blk * 128 + l * 4) = h2_(v0, v1);
    }
}

// ---------------------------------------------------------------------------
// k2: hidden = LN( tril(S) @ E ) — fp16 mma, K=128 chunks, balanced tile-pairs
// ---------------------------------------------------------------------------
__global__ __launch_bounds__(512) void k2_mma(
    const float* __restrict__ gamma, const float* __restrict__ beta)
{
    extern __shared__ char sm[];
    const uint32_t sb = s2u_(sm);
    float* gsm = (float*)(sm + KOFF_PRM);
    float* bsm = gsm + 256;
    float* ps  = (float*)sm;      // alias A0 (only at epilogue)
    float* pq  = ps + 512;

    const int tid = threadIdx.x, lane = tid & 31, warp = tid >> 5;
    const int g = lane >> 2, t = lane & 3, wm = warp >> 2, wn = warp & 3;
    if (tid < 256) { gsm[tid] = gamma[tid]; bsm[tid] = beta[tid]; }

    const int b = blockIdx.y;
    const char* Bbase = (const char*)g_embTH + (size_t)b * D_ * L_ * 2;

    for (int ph = 0; ph < 2; ++ph) {
        const int ib = ph == 0 ? 15 - (int)blockIdx.x : (int)blockIdx.x;
        const int i0 = ib * 128;
        const int nk = ib + 1;                                  // K=128 chunks
        const char* Abase = (const char*)g_scoreH + (size_t)(b * L_ + i0) * L_ * 2;

        auto pref = [&](int kt, uint32_t ao, uint32_t bo) {
            const int j0b = kt * 256;   // byte offset of chunk within row
#pragma unroll
            for (int sub = 0; sub < 2; ++sub) {
                const uint32_t asub = ao + sub * 16384;
                const uint32_t bsub = bo + sub * 32768;
                const int jb = j0b + sub * 128;
#pragma unroll
                for (int q = 0; q < 2; ++q) {
                    const int c = tid + 512 * q;
                    const int r = c >> 3, u = (c & 7) * 16;
                    cpa16_(sb + asub + r * 128 + (u ^ ((r & 7) << 4)),
                           Abase + (size_t)r * (L_ * 2) + jb + u);
                }
#pragma unroll
                for (int q = 0; q < 4; ++q) {
                    const int c = tid + 512 * q;
                    const int n = c >> 3, u = (c & 7) * 16;
                    cpa16_(sb + bsub + n * 128 + (u ^ ((n & 7) << 4)),
                           Bbase + (size_t)n * (L_ * 2) + jb + u);
                }
            }
            CPA_COMMIT_;
        };

        float acc[2][8][4];
#pragma unroll
        for (int mf = 0; mf < 2; ++mf)
#pragma unroll
            for (int nf = 0; nf < 8; ++nf)
#pragma unroll
                for (int e = 0; e < 4; ++e) acc[mf][nf][e] = 0.f;

        __syncthreads();               // params ready / ps-pq alias released
        pref(0, KOFF_A0, KOFF_B0);
        CPA_WAIT0_;
        __syncthreads();

        for (int kt = 0; kt < nk; ++kt) {
            const int s = kt & 1;
            const uint32_t ao = s ? KOFF_A1 : KOFF_A0;
            const uint32_t bo = s ? KOFF_B1 : KOFF_B0;
            if (kt + 1 < nk) pref(kt + 1, s ? KOFF_A0 : KOFF_A1, s ? KOFF_B0 : KOFF_B1);
#pragma unroll
            for (int sub = 0; sub < 2; ++sub) {
                const char* Ab = sm + ao + sub * 16384;
                const char* Bb = sm + bo + sub * 32768;
#pragma unroll
                for (int s2 = 0; s2 < 2; ++s2) {
                    const int toff = t * 32 + s2 * 16;
                    uint4 ar[2][2];
#pragma unroll
                    for (int mf = 0; mf < 2; ++mf) {
                        const int r0 = wm * 32 + mf * 16 + g;
                        ar[mf][0] = *(const uint4*)(Ab + r0 * 128 + (toff ^ ((r0 & 7) << 4)));
                        const int r1 = r0 + 8;
                        ar[mf][1] = *(const uint4*)(Ab + r1 * 128 + (toff ^ ((r1 & 7) << 4)));
                    }
#pragma unroll
                    for (int nf = 0; nf < 8; ++nf) {
                        const int n = wn * 64 + nf * 8 + g;
                        const uint4 br = *(const uint4*)(Bb + n * 128 + (toff ^ ((n & 7) << 4)));
                        mma16_(acc[0][nf], ar[0][0].x, ar[0][1].x, ar[0][0].y, ar[0][1].y, br.x, br.y);
                        mma16_(acc[1][nf], ar[1][0].x, ar[1][1].x, ar[1][0].y, ar[1][1].y, br.x, br.y);
                        mma16_(acc[0][nf], ar[0][0].z, ar[0][1].z, ar[0][0].w, ar[0][1].w, br.z, br.w);
                        mma16_(acc[1][nf], ar[1][0].z, ar[1][1].z, ar[1][0].w, ar[1][1].w, br.z, br.w);
                    }
                }
            }
            CPA_WAIT0_;
            __syncthreads();
        }

        // LN epilogue
#pragma unroll
        for (int mf = 0; mf < 2; ++mf)
#pragma unroll
            for (int h = 0; h < 2; ++h) {
                float s = 0.f, q2 = 0.f;
#pragma unroll
                for (int nf = 0; nf < 8; ++nf) {
                    const float v0 = acc[mf][nf][2 * h], v1 = acc[mf][nf][2 * h + 1];
                    s += v0 + v1;
                    q2 = fmaf(v0, v0, fmaf(v1, v1, q2));
                }
                s  += __shfl_xor_sync(0xffffffffu, s, 1);
                s  += __shfl_xor_sync(0xffffffffu, s, 2);
                q2 += __shfl_xor_sync(0xffffffffu, q2, 1);
                q2 += __shfl_xor_sync(0xffffffffu, q2, 2);
                if (t == 0) {
                    const int r = wm * 32 + mf * 16 + h * 8 + g;
                    ps[r * 4 + wn] = s; pq[r * 4 + wn] = q2;
                }
            }
        __syncthreads();

#pragma unroll
        for (int mf = 0; mf < 2; ++mf)
#pragma unroll
            for (int h = 0; h < 2; ++h) {
                const int r = wm * 32 + mf * 16 + h * 8 + g;
                const float su = ps[r * 4] + ps[r * 4 + 1] + ps[r * 4 + 2] + ps[r * 4 + 3];
                const float sq = pq[r * 4] + pq[r * 4 + 1] + pq[r * 4 + 2] + pq[r * 4 + 3];
                const float mu  = su * (1.f / 256.f);
                const float var = fmaxf(sq * (1.f / 256.f) - mu * mu, 0.f);
                const float rs  = rsqrtf(var + 1e-6f);
                char* dst = (char*)g_hiddenH + (size_t)(b * L_ + i0 + r) * 512;
#pragma unroll
                for (int nf = 0; nf < 8; ++nf) {
                    const int c = wn * 64 + nf * 8 + 2 * t;
                    const float o0 = (acc[mf][nf][2 * h + 0] - mu) * rs * gsm[c] + bsm[c];
                    const float o1 = (acc[mf][nf][2 * h + 1] - mu) * rs * gsm[c + 1] + bsm[c + 1];
                    const int p = (c & 63) >> 1;
                    const int pp = (p & 3) * 8 + (p >> 2);
                    *(uint32_t*)(dst + (c >> 6) * 128 + pp * 4) = h2_(o0, o1);
                }
            }
    }
}

// ---------------------------------------------------------------------------
// k3: out = softplus( w_time . relu([noise|hidden] @ [Wn;Wi]^T) + b )
// K=512 -> 4 chunks of 128.
// ---------------------------------------------------------------------------
__global__ __launch_bounds__(512) void k3_mma(
    const float* __restrict__ wt, const float* __restrict__ btime,
    float* __restrict__ out)
{
    extern __shared__ char sm[];
    const uint32_t sb = s2u_(sm);
    float* wsm = (float*)(sm + KOFF_PRM);
    float* pp  = (float*)sm;   // alias A0 after mainloop

    const int tid = threadIdx.x, lane = tid & 31, warp = tid >> 5;
    const int g = lane >> 2, t = lane & 3, wm = warp >> 2, wn = warp & 3;
    if (tid < 256) wsm[tid] = wt[tid];

    const int b  = blockIdx.y;
    const int i0 = blockIdx.x * 128;

    auto pref = [&](int kt, uint32_t ao, uint32_t bo) {
#pragma unroll
        for (int sub = 0; sub < 2; ++sub) {
            const int ko = 2 * kt + sub;     // 64-wide sub-chunk index (0..7)
            const uint32_t asub = ao + sub * 16384;
            const uint32_t bsub = bo + sub * 32768;
            const char* Asrc = (ko < 4)
                ? (const char*)g_noiseH + (size_t)(b * L_ + i0) * 512 + ko * 128
                : (const char*)g_hiddenH + (size_t)(b * L_ + i0) * 512 + (ko - 4) * 128;
#pragma unroll
            for (int q = 0; q < 2; ++q) {
                const int c = tid + 512 * q;
                const int r = c >> 3, u = (c & 7) * 16;
                cpa16_(sb + asub + r * 128 + (u ^ ((r & 7) << 4)), Asrc + (size_t)r * 512 + u);
            }
#pragma unroll
            for (int q = 0; q < 4; ++q) {
                const int c = tid + 512 * q;
                const int n = c >> 3, u = (c & 7) * 16;
                cpa16_(sb + bsub + n * 128 + (u ^ ((n & 7) << 4)),
                       (const char*)g_WpH + (size_t)n * 1024 + ko * 128 + u);
            }
        }
        CPA_COMMIT_;
    };

    float acc[2][8][4];
#pragma unroll
    for (int mf = 0; mf < 2; ++mf)
#pragma unroll
        for (int nf = 0; nf < 8; ++nf)
#pragma unroll
            for (int e = 0; e < 4; ++e) acc[mf][nf][e] = 0.f;

    __syncthreads();
    pref(0, KOFF_A0, KOFF_B0);
    CPA_WAIT0_;
    __syncthreads();

    for (int kt = 0; kt < 4; ++kt) {
        const int s = kt & 1;
        const uint32_t ao = s ? KOFF_A1 : KOFF_A0;
        const uint32_t bo = s ? KOFF_B1 : KOFF_B0;
        if (kt < 3) pref(kt + 1, s ? KOFF_A0 : KOFF_A1, s ? KOFF_B0 : KOFF_B1);
#pragma unroll
        for (int sub = 0; sub < 2; ++sub) {
            const char* Ab = sm + ao + sub * 16384;
            const char* Bb = sm + bo + sub * 32768;
#pragma unroll
            for (int s2 = 0; s2 < 2; ++s2) {
                const int toff = t * 32 + s2 * 16;
                uint4 ar[2][2];
#pragma unroll
                for (int mf = 0; mf < 2; ++mf) {
                    const int r0 = wm * 32 + mf * 16 + g;
                    ar[mf][0] = *(const uint4*)(Ab + r0 * 128 + (toff ^ ((r0 & 7) << 4)));
                    const int r1 = r0 + 8;
                    ar[mf][1] = *(const uint4*)(Ab + r1 * 128 + (toff ^ ((r1 & 7) << 4)));
                }
#pragma unroll
                for (int nf = 0; nf < 8; ++nf) {
                    const int n = wn * 64 + nf * 8 + g;
                    const uint4 br = *(const uint4*)(Bb + n * 128 + (toff ^ ((n & 7) << 4)));
                    mma16_(acc[0][nf], ar[0][0].x, ar[0][1].x, ar[0][0].y, ar[0][1].y, br.x, br.y);
                    mma16_(acc[1][nf], ar[1][0].x, ar[1][1].x, ar[1][0].y, ar[1][1].y, br.x, br.y);
                    mma16_(acc[0][nf], ar[0][0].z, ar[0][1].z, ar[0][0].w, ar[0][1].w, br.z, br.w);
                    mma16_(acc[1][nf], ar[1][0].z, ar[1][1].z, ar[1][0].w, ar[1][1].w, br.z, br.w);
                }
            }
        }
        CPA_WAIT0_;
        __syncthreads();
    }

    // epilogue: relu + dot(w_time) partials -> quad reduce -> smem -> softplus
#pragma unroll
    for (int mf = 0; mf < 2; ++mf)
#pragma unroll
        for (int h = 0; h < 2; ++h) {
            float p = 0.f;
#pragma unroll
            for (int nf = 0; nf < 8; ++nf)
#pragma unroll
                for (int e = 0; e < 2; ++e) {
                    const int c = wn * 64 + nf * 8 + 2 * t + e;
                    p = fmaf(wsm[c], fmaxf(acc[mf][nf][2 * h + e], 0.f), p);
                }
            p += __shfl_xor_sync(0xffffffffu, p, 1);
            p += __shfl_xor_sync(0xffffffffu, p, 2);
            if (t == 0) pp[(wm * 32 + mf * 16 + h * 8 + g) * 4 + wn] = p;
        }
    __syncthreads();
    if (tid < 128) {
        const float s = pp[tid * 4] + pp[tid * 4 + 1] + pp[tid * 4 + 2] + pp[tid * 4 + 3];
        out[b * L_ + i0 + tid] = softplusf_(s + btime[0]);
    }
}

// ---------------------------------------------------------------------------
// Input order: 0 event_type (unused), 1 event_time, 2 noise, 3 gate_params,
// 4 length_scale, 5 Wn, 6 Wi, 7 w_time, 8 b_time, 9 ln_gamma, 10 ln_beta.
// ---------------------------------------------------------------------------
extern "C" void kernel_launch(void* const* d_in, const int* in_sizes, int n_in,
                              void* d_out, int out_size) {
    const float* et    = (const float*)d_in[1];
    const float* noise = (const float*)d_in[2];
    const float* gp    = (const float*)d_in[3];
    const float* lsc   = (const float*)d_in[4];
    const float* Wn    = (const float*)d_in[5];
    const float* Wi    = (const float*)d_in[6];
    const float* wt    = (const float*)d_in[7];
    const float* bt    = (const float*)d_in[8];
    const float* gam   = (const float*)d_in[9];
    const float* bet   = (const float*)d_in[10];
    float* out = (float*)d_out;

    cudaFuncSetAttribute(k2_mma, cudaFuncAttributeMaxDynamicSharedMemorySize, KSM_TOT);
    cudaFuncSetAttribute(k3_mma, cudaFuncAttributeMaxDynamicSharedMemorySize, KSM_TOT);

    prep_kernel<<<NB_TOT, 256>>>(et, gp, lsc, noise, Wn, Wi);
    k2_mma<<<dim3(8, B_), 512, KSM_TOT>>>(gam, bet);
    k3_mma<<<dim3(16, B_), 512, KSM_TOT>>>(wt, bt, out);
}

// round 17
// speedup vs baseline: 1.4988x; 1.0143x over previous
#include <cuda_runtime.h>
#include <cuda_fp16.h>
#include <math.h>
#include <stdint.h>

#define B_ 16
#define L_ 2048
#define D_ 256

// Scratch (static device arrays — no allocation allowed)
__device__ __align__(16) __half g_scoreH[(size_t)B_ * L_ * L_];   // [b][i][j-perm], tril(+zero superdiag)
__device__ __align__(16) __half g_embTH[(size_t)B_ * D_ * L_];    // [b][d][j-perm]
__device__ __align__(16) __half g_hiddenH[(size_t)B_ * L_ * D_];  // [b][i][k-perm]
__device__ __align__(16) __half g_noiseH[(size_t)B_ * L_ * D_];   // [b][i][k-perm]
__device__ __align__(16) __half g_WpH[512 * 256];                 // [n][k=512 perm]

// ---------------------------------------------------------------------------
// helpers
// ---------------------------------------------------------------------------
__device__ __forceinline__ float softplusf_(float x) {
    return fmaxf(x, 0.f) + log1pf(__expf(-fabsf(x)));
}
__device__ __forceinline__ float sigmoidf_(float x) {
    return 1.f / (1.f + __expf(-x));
}
__device__ __forceinline__ uint32_t h2_(float lo, float hi) {
    __half2 h = __floats2half2_rn(lo, hi);
    return *(uint32_t*)&h;
}
__device__ __forceinline__ uint32_t s2u_(const void* p) {
    uint32_t a;
    asm("{ .reg .u64 t; cvta.to.shared.u64 t, %1; cvt.u32.u64 %0, t; }" : "=r"(a) : "l"(p));
    return a;
}
__device__ __forceinline__ void cpa16_(uint32_t dst, const void* src) {
    asm volatile("cp.async.cg.shared.global [%0], [%1], 16;" :: "r"(dst), "l"(src) : "memory");
}
#define CPA_COMMIT_ asm volatile("cp.async.commit_group;" ::: "memory")
#define CPA_WAIT0_  asm volatile("cp.async.wait_group 0;" ::: "memory")

__device__ __forceinline__ void mma16_(float* c, uint32_t a0, uint32_t a1, uint32_t a2,
                                       uint32_t a3, uint32_t b0, uint32_t b1) {
    asm volatile(
        "mma.sync.aligned.m16n8k16.row.col.f32.f16.f16.f32 "
        "{%0,%1,%2,%3}, {%4,%5,%6,%7}, {%8,%9}, {%0,%1,%2,%3};"
        : "+f"(c[0]), "+f"(c[1]), "+f"(c[2]), "+f"(c[3])
        : "r"(a0), "r"(a1), "r"(a2), "r"(a3), "r"(b0), "r"(b1));
}

// K=128 chunks, each = two 64-k sub-tiles with the proven XOR-16 swizzle layout.
// smem: A 2x32KB | B 2x64KB | params 2KB  (192KB stages + 2KB)
#define KOFF_A0  0
#define KOFF_A1  32768
#define KOFF_B0  65536
#define KOFF_B1  131072
#define KOFF_PRM 196608
#define KSM_TOT  198656

// ---------------------------------------------------------------------------
// fused prep kernel: sections (blockIdx ranges): scores | embTH | noiseH | wpH
// Score section: direct computation into final permuted layout — no smem
// staging, no syncs. Thread (w,l) owns phys pair-slot l; its two logical j's
// are fixed; loops over 8 rows emitting one packed uint32 each (coalesced).
// ---------------------------------------------------------------------------
#define NB_SCORE (528 * B_)                       // 8448
#define NB_EMB   ((B_ * D_ * L_ / 2) / 256)       // 16384
#define NB_NOISE ((B_ * L_ * D_ / 2) / 256)       // 16384
#define NB_WP    ((256 * 512 / 2) / 256)          // 256
#define NB_TOT   (NB_SCORE + NB_EMB + NB_NOISE + NB_WP)

__global__ __launch_bounds__(256) void prep_kernel(
    const float* __restrict__ et, const float* __restrict__ gp,
    const float* __restrict__ lsc, const float* __restrict__ noise,
    const float* __restrict__ Wn, const float* __restrict__ Wi)
{
    const int bid = blockIdx.x;
    const int tid = threadIdx.x;

    if (bid < NB_SCORE) {
        // ---- scores: lower-triangle 64x64 tiles (+zero superdiag tiles) ----
        const int b = bid / 528, tt = bid % 528;
        int it = (int)((sqrtf(8.f * (float)tt + 1.f) - 1.f) * 0.5f);
        while ((it + 1) * (it + 2) / 2 <= tt) ++it;
        while (it * (it + 1) / 2 > tt) --it;
        const int jt = tt - it * (it + 1) / 2;

        const float ls      = softplusf_(lsc[0]);
        const float inv_ls2 = 1.f / (ls * ls);
        const float inv_s   = 1.f / sigmoidf_(gp[1]);
        const float c1      = inv_s * 0.005f;
        const float c0      = -sigmoidf_(gp[0]) * inv_s;
        const float ce      = -inv_ls2 * 1.4426950408889634f;   // fold log2(e) into exp2

        const int w = tid >> 5, l = tid & 31;
        const int p = (l & 7) * 4 + (l >> 3);     // inverse pair-perm
        const int j0 = jt * 64 + 2 * p;           // logical j of lo half
        const float tj0 = __ldg(&et[b * L_ + j0]);
        const float tj1 = __ldg(&et[b * L_ + j0 + 1]);

        char* base = (char*)g_scoreH + ((size_t)(b * L_ + it * 64) * L_ + jt * 64) * 2;
#pragma unroll
        for (int rr = 0; rr < 8; ++rr) {
            const int r  = w * 8 + rr;
            const int ig = it * 64 + r;
            const float ti = __ldg(&et[b * L_ + ig]);   // warp-broadcast
            float sv[2];
#pragma unroll
            for (int e = 0; e < 2; ++e) {
                const float dd = fabsf(ti - (e ? tj1 : tj0));
                float kv;
                asm("ex2.approx.f32 %0, %1;" : "=f"(kv) : "f"(dd * dd * ce));
                float th;
                asm("tanh.approx.f32 %0, %1;" : "=f"(th) : "f"(fmaf(dd, c1, c0)));
                float s = fmaf(kv, th, kv);
                if (j0 + e > ig) s = 0.f;   // causal (keep diagonal)
                sv[e] = s;
            }
            *(uint32_t*)(base + (size_t)r * (L_ * 2) + l * 4) = h2_(sv[0], sv[1]);
        }
        if (it == jt && it < 31) {   // zero the tile right of the diagonal
            char* zb = (char*)g_scoreH + ((size_t)(b * L_ + it * 64) * L_ + (jt + 1) * 64) * 2;
#pragma unroll
            for (int rr = 0; rr < 8; ++rr) {
                const int r = w * 8 + rr;
                *(uint32_t*)(zb + (size_t)r * (L_ * 2) + l * 4) = 0u;
            }
        }
    } else if (bid < NB_SCORE + NB_EMB) {
        // ---- emb^T (half, pair-permuted along j) ----
        const int idx = (bid - NB_SCORE) * 256 + tid;
        const int l = idx & 31, blk = (idx >> 5) & 31, d = (idx >> 10) & 255, b = idx >> 18;
        const int p = (l & 7) * 4 + (l >> 3);
        const int j = blk * 64 + 2 * p;
        const float f = exp2f(-0.10381025296522991f * (float)d);
        const float a0 = __ldg(&et[b * L_ + j]) * f;
        const float a1 = __ldg(&et[b * L_ + j + 1]) * f;
        const float v0 = (d & 1) ? cosf(a0) : sinf(a0);
        const float v1 = (d & 1) ? cosf(a1) : sinf(a1);
        *(uint32_t*)((char*)g_embTH + ((size_t)(b * 256 + d) * L_ + blk * 64) * 2 + l * 4) =
            h2_(v0, v1);
    } else if (bid < NB_SCORE + NB_EMB + NB_NOISE) {
        // ---- noise (half, pair-permuted along k) ----
        const int idx = (bid - NB_SCORE - NB_EMB) * 256 + tid;
        const int l = idx & 31, blk = (idx >> 5) & 3, row = idx >> 7;
        const int p = (l & 7) * 4 + (l >> 3);
        const int k = blk * 64 + 2 * p;
        const float v0 = __ldg(&noise[(size_t)row * 256 + k]);
        const float v1 = __ldg(&noise[(size_t)row * 256 + k + 1]);
        *(uint32_t*)((char*)g_noiseH + (size_t)row * 512 + blk * 128 + l * 4) = h2_(v0, v1);
    } else {
        // ---- W = [Wn | Wi] rows (half, pair-permuted along k) ----
        const int idx = (bid - NB_SCORE - NB_EMB - NB_NOISE) * 256 + tid;
        const int l = idx & 31, blk = (idx >> 5) & 7, n = idx >> 8;
        const int p = (l & 7) * 4 + (l >> 3);
        const int k = blk * 64 + 2 * p;
        const float v0 = (k < 256) ? __ldg(&Wn[n * 256 + k]) : __ldg(&Wi[n * 256 + k - 256]);
        const float v1 = (k + 1 < 256) ? __ldg(&Wn[n * 256 + k + 1])
                                       : __ldg(&Wi[n * 256 + k + 1 - 256]);
        *(uint32_t*)((char*)g_WpH + (size_t)n * 1024 + blk * 128 + l * 4) = h2_(v0, v1);
    }
}

// ---------------------------------------------------------------------------
// k2: hidden = LN( tril(S) @ E ) — fp16 mma, K=128 chunks, balanced tile-pairs
// ---------------------------------------------------------------------------
__global__ __launch_bounds__(512) void k2_mma(
    const float* __restrict__ gamma, const float* __restrict__ beta)
{
    extern __shared__ char sm[];
    const uint32_t sb = s2u_(sm);
    float* gsm = (float*)(sm + KOFF_PRM);
    float* bsm = gsm + 256;
    float* ps  = (float*)sm;      // alias A0 (only at epilogue)
    float* pq  = ps + 512;

    const int tid = threadIdx.x, lane = tid & 31, warp = tid >> 5;
    const int g = lane >> 2, t = lane & 3, wm = warp >> 2, wn = warp & 3;
    if (tid < 256) { gsm[tid] = gamma[tid]; bsm[tid] = beta[tid]; }

    const int b = blockIdx.y;
    const char* Bbase = (const char*)g_embTH + (size_t)b * D_ * L_ * 2;

    for (int ph = 0; ph < 2; ++ph) {
        const int ib = ph == 0 ? 15 - (int)blockIdx.x : (int)blockIdx.x;
        const int i0 = ib * 128;
        const int nk = ib + 1;                                  // K=128 chunks
        const char* Abase = (const char*)g_scoreH + (size_t)(b * L_ + i0) * L_ * 2;

        auto pref = [&](int kt, uint32_t ao, uint32_t bo) {
            const int j0b = kt * 256;   // byte offset of chunk within row
#pragma unroll
            for (int sub = 0; sub < 2; ++sub) {
                const uint32_t asub = ao + sub * 16384;
                const uint32_t bsub = bo + sub * 32768;
                const int jb = j0b + sub * 128;
#pragma unroll
                for (int q = 0; q < 2; ++q) {
                    const int c = tid + 512 * q;
                    const int r = c >> 3, u = (c & 7) * 16;
                    cpa16_(sb + asub + r * 128 + (u ^ ((r & 7) << 4)),
                           Abase + (size_t)r * (L_ * 2) + jb + u);
                }
#pragma unroll
                for (int q = 0; q < 4; ++q) {
                    const int c = tid + 512 * q;
                    const int n = c >> 3, u = (c & 7) * 16;
                    cpa16_(sb + bsub + n * 128 + (u ^ ((n & 7) << 4)),
                           Bbase + (size_t)n * (L_ * 2) + jb + u);
                }
            }
            CPA_COMMIT_;
        };

        float acc[2][8][4];
#pragma unroll
        for (int mf = 0; mf < 2; ++mf)
#pragma unroll
            for (int nf = 0; nf < 8; ++nf)
#pragma unroll
                for (int e = 0; e < 4; ++e) acc[mf][nf][e] = 0.f;

        __syncthreads();               // params ready / ps-pq alias released
        pref(0, KOFF_A0, KOFF_B0);
        CPA_WAIT0_;
        __syncthreads();

        for (int kt = 0; kt < nk; ++kt) {
            const int s = kt & 1;
            const uint32_t ao = s ? KOFF_A1 : KOFF_A0;
            const uint32_t bo = s ? KOFF_B1 : KOFF_B0;
            if (kt + 1 < nk) pref(kt + 1, s ? KOFF_A0 : KOFF_A1, s ? KOFF_B0 : KOFF_B1);
#pragma unroll
            for (int sub = 0; sub < 2; ++sub) {
                const char* Ab = sm + ao + sub * 16384;
                const char* Bb = sm + bo + sub * 32768;
#pragma unroll
                for (int s2 = 0; s2 < 2; ++s2) {
                    const int toff = t * 32 + s2 * 16;
                    uint4 ar[2][2];
#pragma unroll
                    for (int mf = 0; mf < 2; ++mf) {
                        const int r0 = wm * 32 + mf * 16 + g;
                        ar[mf][0] = *(const uint4*)(Ab + r0 * 128 + (toff ^ ((r0 & 7) << 4)));
                        const int r1 = r0 + 8;
                        ar[mf][1] = *(const uint4*)(Ab + r1 * 128 + (toff ^ ((r1 & 7) << 4)));
                    }
#pragma unroll
                    for (int nf = 0; nf < 8; ++nf) {
                        const int n = wn * 64 + nf * 8 + g;
                        const uint4 br = *(const uint4*)(Bb + n * 128 + (toff ^ ((n & 7) << 4)));
                        mma16_(acc[0][nf], ar[0][0].x, ar[0][1].x, ar[0][0].y, ar[0][1].y, br.x, br.y);
                        mma16_(acc[1][nf], ar[1][0].x, ar[1][1].x, ar[1][0].y, ar[1][1].y, br.x, br.y);
                        mma16_(acc[0][nf], ar[0][0].z, ar[0][1].z, ar[0][0].w, ar[0][1].w, br.z, br.w);
                        mma16_(acc[1][nf], ar[1][0].z, ar[1][1].z, ar[1][0].w, ar[1][1].w, br.z, br.w);
                    }
                }
            }
            CPA_WAIT0_;
            __syncthreads();
        }

        // LN epilogue
#pragma unroll
        for (int mf = 0; mf < 2; ++mf)
#pragma unroll
            for (int h = 0; h < 2; ++h) {
                float s = 0.f, q2 = 0.f;
#pragma unroll
                for (int nf = 0; nf < 8; ++nf) {
                    const float v0 = acc[mf][nf][2 * h], v1 = acc[mf][nf][2 * h + 1];
                    s += v0 + v1;
                    q2 = fmaf(v0, v0, fmaf(v1, v1, q2));
                }
                s  += __shfl_xor_sync(0xffffffffu, s, 1);
                s  += __shfl_xor_sync(0xffffffffu, s, 2);
                q2 += __shfl_xor_sync(0xffffffffu, q2, 1);
                q2 += __shfl_xor_sync(0xffffffffu, q2, 2);
                if (t == 0) {
                    const int r = wm * 32 + mf * 16 + h * 8 + g;
                    ps[r * 4 + wn] = s; pq[r * 4 + wn] = q2;
                }
            }
        __syncthreads();

#pragma unroll
        for (int mf = 0; mf < 2; ++mf)
#pragma unroll
            for (int h = 0; h < 2; ++h) {
                const int r = wm * 32 + mf * 16 + h * 8 + g;
                const float su = ps[r * 4] + ps[r * 4 + 1] + ps[r * 4 + 2] + ps[r * 4 + 3];
                const float sq = pq[r * 4] + pq[r * 4 + 1] + pq[r * 4 + 2] + pq[r * 4 + 3];
                const float mu  = su * (1.f / 256.f);
                const float var = fmaxf(sq * (1.f / 256.f) - mu * mu, 0.f);
                const float rs  = rsqrtf(var + 1e-6f);
                char* dst = (char*)g_hiddenH + (size_t)(b * L_ + i0 + r) * 512;
#pragma unroll
                for (int nf = 0; nf < 8; ++nf) {
                    const int c = wn * 64 + nf * 8 + 2 * t;
                    const float o0 = (acc[mf][nf][2 * h + 0] - mu) * rs * gsm[c] + bsm[c];
                    const float o1 = (acc[mf][nf][2 * h + 1] - mu) * rs * gsm[c + 1] + bsm[c + 1];
                    const int p = (c & 63) >> 1;
                    const int pp = (p & 3) * 8 + (p >> 2);
                    *(uint32_t*)(dst + (c >> 6) * 128 + pp * 4) = h2_(o0, o1);
                }
            }
    }
}

// ---------------------------------------------------------------------------
// k3: out = softplus( w_time . relu([noise|hidden] @ [Wn;Wi]^T) + b )
// K=512 -> 4 chunks of 128.
// ---------------------------------------------------------------------------
__global__ __launch_bounds__(512) void k3_mma(
    const float* __restrict__ wt, const float* __restrict__ btime,
    float* __restrict__ out)
{
    extern __shared__ char sm[];
    const uint32_t sb = s2u_(sm);
    float* wsm = (float*)(sm + KOFF_PRM);
    float* pp  = (float*)sm;   // alias A0 after mainloop

    const int tid = threadIdx.x, lane = tid & 31, warp = tid >> 5;
    const int g = lane >> 2, t = lane & 3, wm = warp >> 2, wn = warp & 3;
    if (tid < 256) wsm[tid] = wt[tid];

    const int b  = blockIdx.y;
    const int i0 = blockIdx.x * 128;

    auto pref = [&](int kt, uint32_t ao, uint32_t bo) {
#pragma unroll
        for (int sub = 0; sub < 2; ++sub) {
            const int ko = 2 * kt + sub;     // 64-wide sub-chunk index (0..7)
            const uint32_t asub = ao + sub * 16384;
            const uint32_t bsub = bo + sub * 32768;
            const char* Asrc = (ko < 4)
                ? (const char*)g_noiseH + (size_t)(b * L_ + i0) * 512 + ko * 128
                : (const char*)g_hiddenH + (size_t)(b * L_ + i0) * 512 + (ko - 4) * 128;
#pragma unroll
            for (int q = 0; q < 2; ++q) {
                const int c = tid + 512 * q;
                const int r = c >> 3, u = (c & 7) * 16;
                cpa16_(sb + asub + r * 128 + (u ^ ((r & 7) << 4)), Asrc + (size_t)r * 512 + u);
            }
#pragma unroll
            for (int q = 0; q < 4; ++q) {
                const int c = tid + 512 * q;
                const int n = c >> 3, u = (c & 7) * 16;
                cpa16_(sb + bsub + n * 128 + (u ^ ((n & 7) << 4)),
                       (const char*)g_WpH + (size_t)n * 1024 + ko * 128 + u);
            }
        }
        CPA_COMMIT_;
    };

    float acc[2][8][4];
#pragma unroll
    for (int mf = 0; mf < 2; ++mf)
#pragma unroll
        for (int nf = 0; nf < 8; ++nf)
#pragma unroll
            for (int e = 0; e < 4; ++e) acc[mf][nf][e] = 0.f;

    __syncthreads();
    pref(0, KOFF_A0, KOFF_B0);
    CPA_WAIT0_;
    __syncthreads();

    for (int kt = 0; kt < 4; ++kt) {
        const int s = kt & 1;
        const uint32_t ao = s ? KOFF_A1 : KOFF_A0;
        const uint32_t bo = s ? KOFF_B1 : KOFF_B0;
        if (kt < 3) pref(kt + 1, s ? KOFF_A0 : KOFF_A1, s ? KOFF_B0 : KOFF_B1);
#pragma unroll
        for (int sub = 0; sub < 2; ++sub) {
            const char* Ab = sm + ao + sub * 16384;
            const char* Bb = sm + bo + sub * 32768;
#pragma unroll
            for (int s2 = 0; s2 < 2; ++s2) {
                const int toff = t * 32 + s2 * 16;
                uint4 ar[2][2];
#pragma unroll
                for (int mf = 0; mf < 2; ++mf) {
                    const int r0 = wm * 32 + mf * 16 + g;
                    ar[mf][0] = *(const uint4*)(Ab + r0 * 128 + (toff ^ ((r0 & 7) << 4)));
                    const int r1 = r0 + 8;
                    ar[mf][1] = *(const uint4*)(Ab + r1 * 128 + (toff ^ ((r1 & 7) << 4)));
                }
#pragma unroll
                for (int nf = 0; nf < 8; ++nf) {
                    const int n = wn * 64 + nf * 8 + g;
                    const uint4 br = *(const uint4*)(Bb + n * 128 + (toff ^ ((n & 7) << 4)));
                    mma16_(acc[0][nf], ar[0][0].x, ar[0][1].x, ar[0][0].y, ar[0][1].y, br.x, br.y);
                    mma16_(acc[1][nf], ar[1][0].x, ar[1][1].x, ar[1][0].y, ar[1][1].y, br.x, br.y);
                    mma16_(acc[0][nf], ar[0][0].z, ar[0][1].z, ar[0][0].w, ar[0][1].w, br.z, br.w);
                    mma16_(acc[1][nf], ar[1][0].z, ar[1][1].z, ar[1][0].w, ar[1][1].w, br.z, br.w);
                }
            }
        }
        CPA_WAIT0_;
        __syncthreads();
    }

    // epilogue: relu + dot(w_time) partials -> quad reduce -> smem -> softplus
#pragma unroll
    for (int mf = 0; mf < 2; ++mf)
#pragma unroll
        for (int h = 0; h < 2; ++h) {
            float p = 0.f;
#pragma unroll
            for (int nf = 0; nf < 8; ++nf)
#pragma unroll
                for (int e = 0; e < 2; ++e) {
                    const int c = wn * 64 + nf * 8 + 2 * t + e;
                    p = fmaf(wsm[c], fmaxf(acc[mf][nf][2 * h + e], 0.f), p);
                }
            p += __shfl_xor_sync(0xffffffffu, p, 1);
            p += __shfl_xor_sync(0xffffffffu, p, 2);
            if (t == 0) pp[(wm * 32 + mf * 16 + h * 8 + g) * 4 + wn] = p;
        }
    __syncthreads();
    if (tid < 128) {
        const float s = pp[tid * 4] + pp[tid * 4 + 1] + pp[tid * 4 + 2] + pp[tid * 4 + 3];
        out[b * L_ + i0 + tid] = softplusf_(s + btime[0]);
    }
}

// ---------------------------------------------------------------------------
// Input order: 0 event_type (unused), 1 event_time, 2 noise, 3 gate_params,
// 4 length_scale, 5 Wn, 6 Wi, 7 w_time, 8 b_time, 9 ln_gamma, 10 ln_beta.
// ---------------------------------------------------------------------------
extern "C" void kernel_launch(void* const* d_in, const int* in_sizes, int n_in,
                              void* d_out, int out_size) {
    const float* et    = (const float*)d_in[1];
    const float* noise = (const float*)d_in[2];
    const float* gp    = (const float*)d_in[3];
    const float* lsc   = (const float*)d_in[4];
    const float* Wn    = (const float*)d_in[5];
    const float* Wi    = (const float*)d_in[6];
    const float* wt    = (const float*)d_in[7];
    const float* bt    = (const float*)d_in[8];
    const float* gam   = (const float*)d_in[9];
    const float* bet   = (const float*)d_in[10];
    float* out = (float*)d_out;

    cudaFuncSetAttribute(k2_mma, cudaFuncAttributeMaxDynamicSharedMemorySize, KSM_TOT);
    cudaFuncSetAttribute(k3_mma, cudaFuncAttributeMaxDynamicSharedMemorySize, KSM_TOT);

    prep_kernel<<<NB_TOT, 256>>>(et, gp, lsc, noise, Wn, Wi);
    k2_mma<<<dim3(8, B_), 512, KSM_TOT>>>(gam, bet);
    k3_mma<<<dim3(16, B_), 512, KSM_TOT>>>(wt, bt, out);
}